// round 10
// baseline (speedup 1.0000x reference)
#include <cuda_runtime.h>

#define FULLMASK 0xffffffffu
#define NMO_   40
#define ROWS_  16
#define CSTR   12     // floats per stored MO column; column-major smem
#define CPB    32     // configs per block (128 thr = 64 pairs = 32 cfg x 2 spins)
#define TPB    128

// 4-way register select keyed directly on loc bits 1,2 (no shift needed).
__device__ __forceinline__ float sel4loc(float x0, float x1, float x2, float x3, int loc) {
    const float lo = (loc & 2) ? x1 : x0;
    const float hi = (loc & 2) ? x3 : x2;
    return (loc & 4) ? hi : lo;
}

// Pair-cooperative Slater determinants: 2 lanes per 8x8 matrix, 4 rows/lane.
//  - retired rows exactly zero (winner multiplier forced to 1.0 -> bit-exact
//    self-annihilation), so pivot keys need no retirement masks
//  - permutation parity via running seen-mask popcount (no packed-slot state)
//  - shfl source lane = loc directly (mod-width semantics)
__global__ __launch_bounds__(TPB, 12)
void slater_det_kernel(const float* __restrict__ mo,
                       const int*   __restrict__ cup,
                       const int*   __restrict__ cdown,
                       float*       __restrict__ out,
                       int nconf)
{
    __shared__ __align__(16) float mo_sh[2 * NMO_ * CSTR];  // 960 floats
    __shared__ float sh_det[2 * CPB];

    const int b  = blockIdx.y;
    const int c0 = blockIdx.x * CPB;
    const int t  = threadIdx.x;

    // Stage column-major: mo_sh[(s*40+col)*12 + row8] = mo[b, s*8+row8, col]
    {
        const float* src = mo + (size_t)b * (ROWS_ * NMO_);
        #pragma unroll
        for (int idx = t; idx < ROWS_ * NMO_; idx += TPB) {
            const int e   = idx / NMO_;
            const int col = idx % NMO_;
            mo_sh[((e >> 3) * NMO_ + col) * CSTR + (e & 7)] = src[idx];
        }
    }
    __syncthreads();

    const int pairid = t >> 1;            // 0..63
    const int par    = t & 1;             // lane in pair; my rows = par*4 + r
    const int s      = pairid >> 5;       // spin channel
    const int c      = c0 + (pairid & (CPB - 1));

    const int*   cw   = ((s == 0) ? cup : cdown) + c * 8;
    const float* base = mo_sh + s * NMO_ * CSTR + par * 4;  // 16B-aligned

    // Gather: smem column = 8 contiguous rows; my 4 rows = one LDS.128/column.
    float a[4][8];
    {
        int4 ci = __ldg((const int4*)cw);
        const int c4[4] = {ci.x, ci.y, ci.z, ci.w};
        #pragma unroll
        for (int j = 0; j < 4; ++j) {
            const float4 p = *reinterpret_cast<const float4*>(base + c4[j] * CSTR);
            a[0][j] = p.x; a[1][j] = p.y; a[2][j] = p.z; a[3][j] = p.w;
        }
        ci = __ldg((const int4*)cw + 1);
        const int c8[4] = {ci.x, ci.y, ci.z, ci.w};
        #pragma unroll
        for (int j = 0; j < 4; ++j) {
            const float4 p = *reinterpret_cast<const float4*>(base + c8[j] * CSTR);
            a[0][4 + j] = p.x; a[1][4 + j] = p.y; a[2][4 + j] = p.z; a[3][4 + j] = p.w;
        }
    }

    // Row tags: loc = (row<<1)|par, distinct across the 8 global rows.
    const int l0 = par, l1 = par | 2, l2 = par | 4, l3 = par | 6;

    float det  = 1.0f;
    int   seen = 0;     // bitmask of winning locs so far
    int   cnt  = 0;     // inversion count of the loc sequence

    #pragma unroll
    for (int k = 0; k < 8; ++k) {
        // Key: |a| with low-3 mantissa bits replaced by the tag.
        // Retired rows are exactly 0 -> key = tag only -> never beats live rows.
        const unsigned k0 = (__float_as_uint(a[0][k]) & 0x7FFFFFF8u) | (unsigned)l0;
        const unsigned k1 = (__float_as_uint(a[1][k]) & 0x7FFFFFF8u) | (unsigned)l1;
        const unsigned k2 = (__float_as_uint(a[2][k]) & 0x7FFFFFF8u) | (unsigned)l2;
        const unsigned k3 = (__float_as_uint(a[3][k]) & 0x7FFFFFF8u) | (unsigned)l3;
        unsigned key = (k0 > k1) ? k0 : k1;
        key = (k2 > key) ? k2 : key;
        key = (k3 > key) ? k3 : key;
        {
            const unsigned o = __shfl_xor_sync(FULLMASK, key, 1, 2);
            key = (o > key) ? o : key;
        }
        const int loc = (int)(key & 7u);

        // Parity bookkeeping: inversions against already-retired locs.
        // Bit 'loc' is not yet in 'seen', so >>loc counts strictly-greater.
        cnt  += __popc((unsigned)seen >> loc);
        seen |= 1 << loc;

        // Pivot value broadcast: srcLane = loc (taken mod width 2).
        const float cand = sel4loc(a[0][k], a[1][k], a[2][k], a[3][k], loc);
        const float prk  = __shfl_sync(FULLMASK, cand, loc, 2);
        det *= prk;

        // Multipliers; winner's forced to exactly 1.0 so its row
        // self-annihilates bit-exactly and stays 0 for all later steps.
        const float inv = __frcp_rn(prk);
        const float f0 = (loc == l0) ? 1.0f : a[0][k] * inv;
        const float f1 = (loc == l1) ? 1.0f : a[1][k] * inv;
        const float f2 = (loc == l2) ? 1.0f : a[2][k] * inv;
        const float f3 = (loc == l3) ? 1.0f : a[3][k] * inv;

        #pragma unroll
        for (int j = k + 1; j < 8; ++j) {
            const float cj  = sel4loc(a[0][j], a[1][j], a[2][j], a[3][j], loc);
            const float prj = __shfl_sync(FULLMASK, cj, loc, 2);
            a[0][j] = fmaf(-f0, prj, a[0][j]);
            a[1][j] = fmaf(-f1, prj, a[1][j]);
            a[2][j] = fmaf(-f2, prj, a[2][j]);
            a[3][j] = fmaf(-f3, prj, a[3][j]);
        }
    }

    // loc->globalrow is a 3-bit rotation (two 3-cycles = even permutation),
    // so the loc-sequence inversion parity equals the row-permutation parity.
    det = (cnt & 1) ? -det : det;

    if (par == 0) sh_det[pairid] = det;
    __syncthreads();

    // Combine spins; coalesced 128B store per block.
    if (t < CPB)
        out[(size_t)b * nconf + c0 + t] = sh_det[t] * sh_det[CPB + t];
}

extern "C" void kernel_launch(void* const* d_in, const int* in_sizes, int n_in,
                              void* d_out, int out_size)
{
    const float* mo    = (const float*)d_in[0];  // (B, 16, 40) f32
    const int*   cup   = (const int*)  d_in[1];  // (C, 8) i32
    const int*   cdown = (const int*)  d_in[2];  // (C, 8) i32
    float*       out   = (float*)d_out;          // (B, C) f32

    const int B = in_sizes[0] / (ROWS_ * NMO_);
    const int C = in_sizes[1] / 8;

    dim3 grid(C / CPB, B);
    slater_det_kernel<<<grid, TPB>>>(mo, cup, cdown, out, C);
}

// round 11
// speedup vs baseline: 1.1040x; 1.1040x over previous
#include <cuda_runtime.h>

#define FULLMASK 0xffffffffu
#define NMO_   40
#define ROWS_  16
#define CSTR   12     // floats per stored MO column; column-major smem
#define CPB    32     // configs per block (128 thr = 64 pairs = 32 cfg x 2 spins)
#define TPB    128

// 4-way register select keyed directly on loc bits 1,2 (no shift needed).
__device__ __forceinline__ float sel4loc(float x0, float x1, float x2, float x3, int loc) {
    const float lo = (loc & 2) ? x1 : x0;
    const float hi = (loc & 2) ? x3 : x2;
    return (loc & 4) ? hi : lo;
}

// Pair-cooperative Slater determinants: 2 lanes per 8x8 matrix, 4 rows/lane.
//  - retired rows exactly zero (winner multiplier forced to 1.0 -> bit-exact
//    self-annihilation), so pivot keys need no retirement masks
//  - permutation parity via running seen-mask popcount (no packed-slot state)
//  - shfl source lane = loc directly (mod-width semantics)
// occupancy bound 10 (NOT 12): capping regs at 40 makes ptxas spill, which
// costs more than the occupancy it buys (measured R10: +10% L2, -6us).
__global__ __launch_bounds__(TPB, 10)
void slater_det_kernel(const float* __restrict__ mo,
                       const int*   __restrict__ cup,
                       const int*   __restrict__ cdown,
                       float*       __restrict__ out,
                       int nconf)
{
    __shared__ __align__(16) float mo_sh[2 * NMO_ * CSTR];  // 960 floats
    __shared__ float sh_det[2 * CPB];

    const int b  = blockIdx.y;
    const int c0 = blockIdx.x * CPB;
    const int t  = threadIdx.x;

    // Stage column-major: mo_sh[(s*40+col)*12 + row8] = mo[b, s*8+row8, col]
    {
        const float* src = mo + (size_t)b * (ROWS_ * NMO_);
        #pragma unroll
        for (int idx = t; idx < ROWS_ * NMO_; idx += TPB) {
            const int e   = idx / NMO_;
            const int col = idx % NMO_;
            mo_sh[((e >> 3) * NMO_ + col) * CSTR + (e & 7)] = src[idx];
        }
    }
    __syncthreads();

    const int pairid = t >> 1;            // 0..63
    const int par    = t & 1;             // lane in pair; my rows = par*4 + r
    const int s      = pairid >> 5;       // spin channel
    const int c      = c0 + (pairid & (CPB - 1));

    const int*   cw   = ((s == 0) ? cup : cdown) + c * 8;
    const float* base = mo_sh + s * NMO_ * CSTR + par * 4;  // 16B-aligned

    // Gather: smem column = 8 contiguous rows; my 4 rows = one LDS.128/column.
    float a[4][8];
    {
        int4 ci = __ldg((const int4*)cw);
        const int c4[4] = {ci.x, ci.y, ci.z, ci.w};
        #pragma unroll
        for (int j = 0; j < 4; ++j) {
            const float4 p = *reinterpret_cast<const float4*>(base + c4[j] * CSTR);
            a[0][j] = p.x; a[1][j] = p.y; a[2][j] = p.z; a[3][j] = p.w;
        }
        ci = __ldg((const int4*)cw + 1);
        const int c8[4] = {ci.x, ci.y, ci.z, ci.w};
        #pragma unroll
        for (int j = 0; j < 4; ++j) {
            const float4 p = *reinterpret_cast<const float4*>(base + c8[j] * CSTR);
            a[0][4 + j] = p.x; a[1][4 + j] = p.y; a[2][4 + j] = p.z; a[3][4 + j] = p.w;
        }
    }

    // Row tags: loc = (row<<1)|par, distinct across the 8 global rows.
    const int l0 = par, l1 = par | 2, l2 = par | 4, l3 = par | 6;

    float det  = 1.0f;
    int   seen = 0;     // bitmask of winning locs so far
    int   cnt  = 0;     // inversion count of the loc sequence

    #pragma unroll
    for (int k = 0; k < 8; ++k) {
        // Key: |a| with low-3 mantissa bits replaced by the tag.
        // Retired rows are exactly 0 -> key = tag only -> never beats live rows.
        const unsigned k0 = (__float_as_uint(a[0][k]) & 0x7FFFFFF8u) | (unsigned)l0;
        const unsigned k1 = (__float_as_uint(a[1][k]) & 0x7FFFFFF8u) | (unsigned)l1;
        const unsigned k2 = (__float_as_uint(a[2][k]) & 0x7FFFFFF8u) | (unsigned)l2;
        const unsigned k3 = (__float_as_uint(a[3][k]) & 0x7FFFFFF8u) | (unsigned)l3;
        unsigned key = (k0 > k1) ? k0 : k1;
        key = (k2 > key) ? k2 : key;
        key = (k3 > key) ? k3 : key;
        {
            const unsigned o = __shfl_xor_sync(FULLMASK, key, 1, 2);
            key = (o > key) ? o : key;
        }
        const int loc = (int)(key & 7u);

        // Parity bookkeeping: inversions against already-retired locs.
        // Bit 'loc' is not yet in 'seen', so >>loc counts strictly-greater.
        cnt  += __popc((unsigned)seen >> loc);
        seen |= 1 << loc;

        // Pivot value broadcast: srcLane = loc (taken mod width 2).
        const float cand = sel4loc(a[0][k], a[1][k], a[2][k], a[3][k], loc);
        const float prk  = __shfl_sync(FULLMASK, cand, loc, 2);
        det *= prk;

        // Multipliers; winner's forced to exactly 1.0 so its row
        // self-annihilates bit-exactly and stays 0 for all later steps.
        const float inv = __frcp_rn(prk);
        const float f0 = (loc == l0) ? 1.0f : a[0][k] * inv;
        const float f1 = (loc == l1) ? 1.0f : a[1][k] * inv;
        const float f2 = (loc == l2) ? 1.0f : a[2][k] * inv;
        const float f3 = (loc == l3) ? 1.0f : a[3][k] * inv;

        #pragma unroll
        for (int j = k + 1; j < 8; ++j) {
            const float cj  = sel4loc(a[0][j], a[1][j], a[2][j], a[3][j], loc);
            const float prj = __shfl_sync(FULLMASK, cj, loc, 2);
            a[0][j] = fmaf(-f0, prj, a[0][j]);
            a[1][j] = fmaf(-f1, prj, a[1][j]);
            a[2][j] = fmaf(-f2, prj, a[2][j]);
            a[3][j] = fmaf(-f3, prj, a[3][j]);
        }
    }

    // loc->globalrow is a 3-bit rotation (two 3-cycles = even permutation),
    // so the loc-sequence inversion parity equals the row-permutation parity.
    det = (cnt & 1) ? -det : det;

    if (par == 0) sh_det[pairid] = det;
    __syncthreads();

    // Combine spins; coalesced 128B store per block.
    if (t < CPB)
        out[(size_t)b * nconf + c0 + t] = sh_det[t] * sh_det[CPB + t];
}

extern "C" void kernel_launch(void* const* d_in, const int* in_sizes, int n_in,
                              void* d_out, int out_size)
{
    const float* mo    = (const float*)d_in[0];  // (B, 16, 40) f32
    const int*   cup   = (const int*)  d_in[1];  // (C, 8) i32
    const int*   cdown = (const int*)  d_in[2];  // (C, 8) i32
    float*       out   = (float*)d_out;          // (B, C) f32

    const int B = in_sizes[0] / (ROWS_ * NMO_);
    const int C = in_sizes[1] / 8;

    dim3 grid(C / CPB, B);
    slater_det_kernel<<<grid, TPB>>>(mo, cup, cdown, out, C);
}